// round 12
// baseline (speedup 1.0000x reference)
#include <cuda_runtime.h>

#define NUM_HEADS 12
#define HD 64
#define BATCH 8
#define HH 32
#define WW 32
#define S 1024          // HH*WW
#define C 768
#define BHN 96          // BATCH*NUM_HEADS

// ---------------- scratch (no allocations allowed) ----------------
__device__ __align__(16) float g_q[(size_t)BHN * S * HD];
__device__ __align__(16) float g_k[(size_t)BHN * S * HD];
__device__ __align__(16) float g_v[(size_t)BHN * S * HD];
__device__ __align__(16) float g_relh[(size_t)BHN * S * HH];
__device__ __align__(16) float g_relw[(size_t)BHN * S * WW];
__device__ __align__(16) float g_att[(size_t)BATCH * S * C];

// ------- 128x128x8 fp32 GEMM, 8x8 microtile, double-buffered smem ---------
// MODE 0: C = A @ B + bias, scatter into g_q/g_k/g_v  (A = x, B = w_qkv)
// MODE 1: C = g_att @ B + bias -> Cout (row-major)     (B = w_proj)
template <int MODE>
__global__ __launch_bounds__(256) void gemm_k(const float* __restrict__ A,
                                              const float* __restrict__ B,
                                              const float* __restrict__ bias,
                                              float* __restrict__ Cout,
                                              int M, int N, int K)
{
    __shared__ __align__(16) float As[2][8][128];
    __shared__ __align__(16) float Bs[2][8][128];

    const float* Ap = (MODE == 1) ? (const float*)g_att : A;

    const int tid = threadIdx.x;
    const int tx = tid & 15, ty = tid >> 4;
    const int bm = blockIdx.y * 128, bn = blockIdx.x * 128;

    float acc[8][8];
#pragma unroll
    for (int i = 0; i < 8; i++)
#pragma unroll
        for (int j = 0; j < 8; j++) acc[i][j] = 0.f;

    const int arow = tid >> 1, acol = (tid & 1) * 4;
    const int brow = tid >> 5, bcol = (tid & 31) * 4;
    const int klast = K - 8;

    // prologue: chunk 0 -> buf 0; preload chunk 1 into regs
    {
        float4 av = *(const float4*)(Ap + (size_t)(bm + arow) * K + acol);
        float4 bv = *(const float4*)(B + (size_t)brow * N + bn + bcol);
        As[0][acol + 0][arow] = av.x;
        As[0][acol + 1][arow] = av.y;
        As[0][acol + 2][arow] = av.z;
        As[0][acol + 3][arow] = av.w;
        *(float4*)&Bs[0][brow][bcol] = bv;
    }
    float4 av = *(const float4*)(Ap + (size_t)(bm + arow) * K + 8 + acol);
    float4 bv = *(const float4*)(B + (size_t)(8 + brow) * N + bn + bcol);
    __syncthreads();

    int buf = 0;
    for (int k0 = 0; k0 < K; k0 += 8) {
        // stage chunk k0+8 into the idle buffer (overlaps with compute below)
        const int nb = buf ^ 1;
        As[nb][acol + 0][arow] = av.x;
        As[nb][acol + 1][arow] = av.y;
        As[nb][acol + 2][arow] = av.z;
        As[nb][acol + 3][arow] = av.w;
        *(float4*)&Bs[nb][brow][bcol] = bv;

        // prefetch chunk k0+16 (clamped; redundant reload on tail is harmless)
        const int kn = (k0 + 16 <= klast) ? k0 + 16 : klast;
        av = *(const float4*)(Ap + (size_t)(bm + arow) * K + kn + acol);
        bv = *(const float4*)(B + (size_t)(kn + brow) * N + bn + bcol);

        // compute current chunk
#pragma unroll
        for (int kk = 0; kk < 8; kk++) {
            float a[8], b[8];
            *(float4*)(a)     = *(const float4*)&As[buf][kk][ty * 8];
            *(float4*)(a + 4) = *(const float4*)&As[buf][kk][ty * 8 + 4];
            *(float4*)(b)     = *(const float4*)&Bs[buf][kk][tx * 8];
            *(float4*)(b + 4) = *(const float4*)&Bs[buf][kk][tx * 8 + 4];
#pragma unroll
            for (int i = 0; i < 8; i++)
#pragma unroll
                for (int j = 0; j < 8; j++)
                    acc[i][j] = fmaf(a[i], b[j], acc[i][j]);
        }
        __syncthreads();    // next buffer staged + current reads done
        buf = nb;
    }

#pragma unroll
    for (int i = 0; i < 8; i++) {
        const int m = bm + ty * 8 + i;
        const int b = m >> 10, s = m & 1023;
#pragma unroll
        for (int j = 0; j < 8; j += 2) {
            const int n = bn + tx * 8 + j;          // even
            const float v0 = acc[i][j + 0] + bias[n];
            const float v1 = acc[i][j + 1] + bias[n + 1];
            float2 st; st.x = v0; st.y = v1;
            if (MODE == 0) {
                // even pair never crosses a head (64) or tensor (768) boundary
                const int t   = n / C;              // 0:q 1:k 2:v
                const int rem = n - t * C;
                const int hh  = rem >> 6;
                const int d   = rem & 63;
                float* dst = (t == 0) ? g_q : (t == 1) ? g_k : g_v;
                *(float2*)(dst + ((size_t)(b * NUM_HEADS + hh) * S + s) * HD + d) = st;
            } else {
                *(float2*)(Cout + (size_t)m * N + n) = st;
            }
        }
    }
}

// ---------------- relative-position bias tables (both modes, one launch) --
__global__ __launch_bounds__(256) void rel_kernel(const float* __restrict__ tabh,
                                                  const float* __restrict__ tabw)
{
    __shared__ float tab[63][65];
    __shared__ float qs[32][65];
    const int bh = blockIdx.y;
    const int h  = blockIdx.x;
    const int mode = blockIdx.z;
    const int tid = threadIdx.x;
    const float* table = mode ? tabw : tabh;

    for (int idx = tid; idx < 63 * 64; idx += 256)
        tab[idx >> 6][idx & 63] = table[idx];
    const float* qbase = g_q + ((size_t)bh * S + h * 32) * HD;
    for (int idx = tid; idx < 32 * 64; idx += 256)
        qs[idx >> 6][idx & 63] = qbase[idx];
    __syncthreads();

    float* out = (mode == 0) ? g_relh : g_relw;
    float* obase = out + ((size_t)bh * 32 + h) * 32 * 32;

    for (int o = tid; o < 1024; o += 256) {
        const int w = o >> 5, j = o & 31;
        const int row = (mode == 0) ? (h - j + 31) : (w - j + 31);
        const float* qr = qs[w];
        const float* tr = tab[row];
        float a0 = 0.f, a1 = 0.f, a2 = 0.f, a3 = 0.f;
#pragma unroll
        for (int d = 0; d < 64; d += 4) {
            a0 = fmaf(qr[d + 0], tr[d + 0], a0);
            a1 = fmaf(qr[d + 1], tr[d + 1], a1);
            a2 = fmaf(qr[d + 2], tr[d + 2], a2);
            a3 = fmaf(qr[d + 3], tr[d + 3], a3);
        }
        obase[o] = (a0 + a1) + (a2 + a3);
    }
}

// ---------------- fused attention (32-key tiles, warp-local softmax) ------
// sc dependencies (QK->softmax, softmax->PV) are intra-warp: row r is
// written by tids 8*(r>>3)..+7 and read by tid r, all in warp r/32.
struct AttSmem {
    float q   [128][65];   // 33280 B
    float sc  [128][33];   // 16896 B
    float kv  [32][65];    //  8320 B
    float rwsT[32][128];   // 16384 B (transposed: [key][query])
    float corr[128];       //   512 B
    float invl[128];       //   512 B
};                         // 75904 B -> 3 blocks/SM with max carveout

__global__ __launch_bounds__(128, 3) void attn_kernel()
{
    extern __shared__ char smem_raw[];
    AttSmem& sm = *reinterpret_cast<AttSmem*>(smem_raw);

    const int bh  = blockIdx.y;
    const int s0  = blockIdx.x * 128;
    const int tid = threadIdx.x;
    const int qty = tid >> 3;
    const int qtx = tid & 7;
    const float scale = 0.125f;

    {
        const float4* qp = (const float4*)(g_q + ((size_t)bh * S + s0) * HD);
#pragma unroll
        for (int u = 0; u < 16; u++) {
            const int idx4 = tid + 128 * u;
            float4 t = qp[idx4];
            const int r = idx4 >> 4, c = (idx4 & 15) * 4;
            sm.q[r][c + 0] = t.x * scale;
            sm.q[r][c + 1] = t.y * scale;
            sm.q[r][c + 2] = t.z * scale;
            sm.q[r][c + 3] = t.w * scale;
        }
    }
    {   // stage rel_w transposed: thread t reads row (s0+t), scatters to col t
        const float4* rp = (const float4*)(g_relw + ((size_t)bh * S + s0 + tid) * 32);
#pragma unroll
        for (int u = 0; u < 8; u++) {
            float4 t = rp[u];
            sm.rwsT[4 * u + 0][tid] = t.x;
            sm.rwsT[4 * u + 1][tid] = t.y;
            sm.rwsT[4 * u + 2][tid] = t.z;
            sm.rwsT[4 * u + 3][tid] = t.w;
        }
    }

    float o[8][8];
#pragma unroll
    for (int i = 0; i < 8; i++)
#pragma unroll
        for (int j = 0; j < 8; j++) o[i][j] = 0.f;

    float mrun = -1e30f, lrun = 0.f;

    // preload K tile 0 into registers
    float4 kreg[4];
    {
        const float4* kp = (const float4*)(g_k + ((size_t)bh * S) * HD);
#pragma unroll
        for (int u = 0; u < 4; u++) kreg[u] = kp[tid + 128 * u];
    }

    for (int kt0 = 0; kt0 < S; kt0 += 32) {
        __syncthreads();            // kv free (prev PV done)

        // ---- stage prefetched K tile ----
#pragma unroll
        for (int u = 0; u < 4; u++) {
            const int idx4 = tid + 128 * u;
            const int r = idx4 >> 4, c = (idx4 & 15) * 4;
            sm.kv[r][c + 0] = kreg[u].x;
            sm.kv[r][c + 1] = kreg[u].y;
            sm.kv[r][c + 2] = kreg[u].z;
            sm.kv[r][c + 3] = kreg[u].w;
        }
        __syncthreads();

        // ---- QK micro-tile: 8q x 4k ----
        {
            float acc[8][4];
#pragma unroll
            for (int i = 0; i < 8; i++)
#pragma unroll
                for (int j = 0; j < 4; j++) acc[i][j] = 0.f;

#pragma unroll 8
            for (int kk = 0; kk < 64; kk++) {
                float a[8], b[4];
#pragma unroll
                for (int i = 0; i < 8; i++) a[i] = sm.q[qty * 8 + i][kk];
#pragma unroll
                for (int j = 0; j < 4; j++) b[j] = sm.kv[qtx * 4 + j][kk];
#pragma unroll
                for (int i = 0; i < 8; i++)
#pragma unroll
                    for (int j = 0; j < 4; j++)
                        acc[i][j] = fmaf(a[i], b[j], acc[i][j]);
            }
#pragma unroll
            for (int i = 0; i < 8; i++)
#pragma unroll
                for (int j = 0; j < 4; j++)
                    sm.sc[qty * 8 + i][qtx * 4 + j] = acc[i][j];
        }

        // ---- V + next-K prefetch (LDG in flight through softmax) ----
        float4 vreg[4];
        {
            const float4* vp = (const float4*)(g_v + ((size_t)bh * S + kt0) * HD);
#pragma unroll
            for (int u = 0; u < 4; u++) vreg[u] = vp[tid + 128 * u];
            const int ktn = (kt0 + 32 < S) ? kt0 + 32 : kt0;
            const float4* kp = (const float4*)(g_k + ((size_t)bh * S + ktn) * HD);
#pragma unroll
            for (int u = 0; u < 4; u++) kreg[u] = kp[tid + 128 * u];
        }

        __syncwarp();               // sc handoff is intra-warp: overlap softmax
                                    // with other warps' QK tails
        // ---- softmax (rhb folded into subtracted max) ----
        {
            const float rhb = g_relh[((size_t)bh * S + s0 + tid) * 32 + (kt0 >> 5)];
            float s[32];
            float mx = -1e30f;
#pragma unroll
            for (int j = 0; j < 32; j++) {
                s[j] = sm.sc[tid][j] + sm.rwsT[j][tid];   // true logit minus rhb
                mx = fmaxf(mx, s[j]);
            }
            const float mnew = fmaxf(mrun, mx + rhb);     // true running max
            const float meff = mnew - rhb;
            const float cf = __expf(mrun - mnew);
            lrun *= cf;
#pragma unroll
            for (int j = 0; j < 32; j++) {
                const float p = __expf(s[j] - meff);
                lrun += p;
                sm.sc[tid][j] = p;
            }
            mrun = mnew;
            sm.corr[tid] = cf;
            if (kt0 == S - 32) sm.invl[tid] = 1.f / lrun;
        }

        __syncthreads();            // all warps past QK kv reads
        // ---- stage V ----
#pragma unroll
        for (int u = 0; u < 4; u++) {
            const int idx4 = tid + 128 * u;
            const int r = idx4 >> 4, c = (idx4 & 15) * 4;
            sm.kv[r][c + 0] = vreg[u].x;
            sm.kv[r][c + 1] = vreg[u].y;
            sm.kv[r][c + 2] = vreg[u].z;
            sm.kv[r][c + 3] = vreg[u].w;
        }
        __syncthreads();            // V visible (sc/corr handoff is intra-warp)

        // ---- PV micro-tile: 8q x 8d ----
        {
            if (kt0 > 0) {          // tile 0: o is all zero, skip rescale
                float c8[8];
#pragma unroll
                for (int i = 0; i < 8; i++) c8[i] = sm.corr[qty * 8 + i];
#pragma unroll
                for (int i = 0; i < 8; i++)
#pragma unroll
                    for (int j = 0; j < 8; j++) o[i][j] *= c8[i];
            }

#pragma unroll 4
            for (int key = 0; key < 32; key++) {
                float vv[8];
#pragma unroll
                for (int j = 0; j < 4; j++) vv[j]     = sm.kv[key][qtx * 4 + j];
#pragma unroll
                for (int j = 0; j < 4; j++) vv[4 + j] = sm.kv[key][32 + qtx * 4 + j];
#pragma unroll
                for (int i = 0; i < 8; i++) {
                    const float p = sm.sc[qty * 8 + i][key];
#pragma unroll
                    for (int j = 0; j < 8; j++)
                        o[i][j] = fmaf(p, vv[j], o[i][j]);
                }
            }
        }
    }

    // ---- epilogue ----
    {
        float inv8[8];
#pragma unroll
        for (int i = 0; i < 8; i++) inv8[i] = sm.invl[qty * 8 + i];
        const int b = bh / NUM_HEADS, head = bh % NUM_HEADS;
#pragma unroll
        for (int i = 0; i < 8; i++) {
            const int qrow = s0 + qty * 8 + i;
            float* dst = g_att + ((size_t)(b * S + qrow)) * C + head * HD;
            float4 t0, t1;
            t0.x = o[i][0] * inv8[i];
            t0.y = o[i][1] * inv8[i];
            t0.z = o[i][2] * inv8[i];
            t0.w = o[i][3] * inv8[i];
            t1.x = o[i][4] * inv8[i];
            t1.y = o[i][5] * inv8[i];
            t1.z = o[i][6] * inv8[i];
            t1.w = o[i][7] * inv8[i];
            *(float4*)(dst + qtx * 4)      = t0;
            *(float4*)(dst + 32 + qtx * 4) = t1;
        }
    }
}

// ---------------- launch ----------------
extern "C" void kernel_launch(void* const* d_in, const int* in_sizes, int n_in,
                              void* d_out, int out_size)
{
    const float* x     = (const float*)d_in[0];
    const float* wqkv  = (const float*)d_in[1];
    const float* bqkv  = (const float*)d_in[2];
    const float* rph   = (const float*)d_in[3];
    const float* rpw   = (const float*)d_in[4];
    const float* wproj = (const float*)d_in[5];
    const float* bproj = (const float*)d_in[6];
    float* out = (float*)d_out;

    // 1) QKV GEMM -> g_q/g_k/g_v  (M=8192, N=2304, K=768)
    dim3 g1(2304 / 128, 8192 / 128);
    gemm_k<0><<<g1, 256>>>(x, wqkv, bqkv, nullptr, BATCH * S, 3 * C, C);

    // 2) relative-position bias tables (h and w in one launch)
    rel_kernel<<<dim3(32, BHN, 2), 256>>>(rph, rpw);

    // 3) fused attention -> g_att
    const size_t attn_smem = sizeof(AttSmem);
    cudaFuncSetAttribute(attn_kernel, cudaFuncAttributeMaxDynamicSharedMemorySize,
                         (int)attn_smem);
    cudaFuncSetAttribute(attn_kernel, cudaFuncAttributePreferredSharedMemoryCarveout,
                         100);   // max shared carveout -> 3 blocks/SM
    attn_kernel<<<dim3(S / 128, BHN), 128, attn_smem>>>();

    // 4) output projection -> d_out  (M=8192, N=768, K=768)
    dim3 g2(768 / 128, 8192 / 128);
    gemm_k<1><<<g2, 256>>>(nullptr, wproj, bproj, out, BATCH * S, C, C);
}

// round 13
// speedup vs baseline: 1.0012x; 1.0012x over previous
#include <cuda_runtime.h>

#define NUM_HEADS 12
#define HD 64
#define BATCH 8
#define HH 32
#define WW 32
#define S 1024          // HH*WW
#define C 768
#define BHN 96          // BATCH*NUM_HEADS

// ---------------- scratch (no allocations allowed) ----------------
__device__ __align__(16) float g_q[(size_t)BHN * S * HD];
__device__ __align__(16) float g_k[(size_t)BHN * S * HD];
__device__ __align__(16) float g_v[(size_t)BHN * S * HD];
__device__ __align__(16) float g_relh[(size_t)BHN * S * HH];
__device__ __align__(16) float g_relw[(size_t)BHN * S * WW];
__device__ __align__(16) float g_att[(size_t)BATCH * S * C];

// ------- 128x128x8 fp32 GEMM, 8x8 microtile, double-buffered smem ---------
// (R11 exact: scalar-store epilogue, regs=126, 2 blocks/SM)
// MODE 0: C = A @ B + bias, scatter into g_q/g_k/g_v  (A = x, B = w_qkv)
// MODE 1: C = g_att @ B + bias -> Cout (row-major)     (B = w_proj)
template <int MODE>
__global__ __launch_bounds__(256) void gemm_k(const float* __restrict__ A,
                                              const float* __restrict__ B,
                                              const float* __restrict__ bias,
                                              float* __restrict__ Cout,
                                              int M, int N, int K)
{
    __shared__ __align__(16) float As[2][8][128];
    __shared__ __align__(16) float Bs[2][8][128];

    const float* Ap = (MODE == 1) ? (const float*)g_att : A;

    const int tid = threadIdx.x;
    const int tx = tid & 15, ty = tid >> 4;
    const int bm = blockIdx.y * 128, bn = blockIdx.x * 128;

    float acc[8][8];
#pragma unroll
    for (int i = 0; i < 8; i++)
#pragma unroll
        for (int j = 0; j < 8; j++) acc[i][j] = 0.f;

    const int arow = tid >> 1, acol = (tid & 1) * 4;
    const int brow = tid >> 5, bcol = (tid & 31) * 4;
    const int klast = K - 8;

    // prologue: chunk 0 -> buf 0; preload chunk 1 into regs
    {
        float4 av = *(const float4*)(Ap + (size_t)(bm + arow) * K + acol);
        float4 bv = *(const float4*)(B + (size_t)brow * N + bn + bcol);
        As[0][acol + 0][arow] = av.x;
        As[0][acol + 1][arow] = av.y;
        As[0][acol + 2][arow] = av.z;
        As[0][acol + 3][arow] = av.w;
        *(float4*)&Bs[0][brow][bcol] = bv;
    }
    float4 av = *(const float4*)(Ap + (size_t)(bm + arow) * K + 8 + acol);
    float4 bv = *(const float4*)(B + (size_t)(8 + brow) * N + bn + bcol);
    __syncthreads();

    int buf = 0;
    for (int k0 = 0; k0 < K; k0 += 8) {
        // stage chunk k0+8 into the idle buffer (overlaps with compute below)
        const int nb = buf ^ 1;
        As[nb][acol + 0][arow] = av.x;
        As[nb][acol + 1][arow] = av.y;
        As[nb][acol + 2][arow] = av.z;
        As[nb][acol + 3][arow] = av.w;
        *(float4*)&Bs[nb][brow][bcol] = bv;

        // prefetch chunk k0+16 (clamped; redundant reload on tail is harmless)
        const int kn = (k0 + 16 <= klast) ? k0 + 16 : klast;
        av = *(const float4*)(Ap + (size_t)(bm + arow) * K + kn + acol);
        bv = *(const float4*)(B + (size_t)(kn + brow) * N + bn + bcol);

        // compute current chunk
#pragma unroll
        for (int kk = 0; kk < 8; kk++) {
            float a[8], b[8];
            *(float4*)(a)     = *(const float4*)&As[buf][kk][ty * 8];
            *(float4*)(a + 4) = *(const float4*)&As[buf][kk][ty * 8 + 4];
            *(float4*)(b)     = *(const float4*)&Bs[buf][kk][tx * 8];
            *(float4*)(b + 4) = *(const float4*)&Bs[buf][kk][tx * 8 + 4];
#pragma unroll
            for (int i = 0; i < 8; i++)
#pragma unroll
                for (int j = 0; j < 8; j++)
                    acc[i][j] = fmaf(a[i], b[j], acc[i][j]);
        }
        __syncthreads();    // next buffer staged + current reads done
        buf = nb;
    }

#pragma unroll
    for (int i = 0; i < 8; i++) {
        const int m = bm + ty * 8 + i;
        const int b = m >> 10, s = m & 1023;
#pragma unroll
        for (int j = 0; j < 8; j++) {
            const int n = bn + tx * 8 + j;
            const float v = acc[i][j] + bias[n];
            if (MODE == 0) {
                const int t   = n / C;          // 0:q 1:k 2:v
                const int rem = n - t * C;
                const int hh  = rem >> 6;       // head
                const int d   = rem & 63;
                float* dst = (t == 0) ? g_q : (t == 1) ? g_k : g_v;
                dst[((size_t)(b * NUM_HEADS + hh) * S + s) * HD + d] = v;
            } else {
                Cout[(size_t)m * N + n] = v;
            }
        }
    }
}

// ---------------- relative-position bias tables (both modes, one launch) --
__global__ __launch_bounds__(256) void rel_kernel(const float* __restrict__ tabh,
                                                  const float* __restrict__ tabw)
{
    __shared__ float tab[63][65];
    __shared__ float qs[32][65];
    const int bh = blockIdx.y;
    const int h  = blockIdx.x;
    const int mode = blockIdx.z;
    const int tid = threadIdx.x;
    const float* table = mode ? tabw : tabh;

    for (int idx = tid; idx < 63 * 64; idx += 256)
        tab[idx >> 6][idx & 63] = table[idx];
    const float* qbase = g_q + ((size_t)bh * S + h * 32) * HD;
    for (int idx = tid; idx < 32 * 64; idx += 256)
        qs[idx >> 6][idx & 63] = qbase[idx];
    __syncthreads();

    float* out = (mode == 0) ? g_relh : g_relw;
    float* obase = out + ((size_t)bh * 32 + h) * 32 * 32;

    for (int o = tid; o < 1024; o += 256) {
        const int w = o >> 5, j = o & 31;
        const int row = (mode == 0) ? (h - j + 31) : (w - j + 31);
        const float* qr = qs[w];
        const float* tr = tab[row];
        float a0 = 0.f, a1 = 0.f, a2 = 0.f, a3 = 0.f;
#pragma unroll
        for (int d = 0; d < 64; d += 4) {
            a0 = fmaf(qr[d + 0], tr[d + 0], a0);
            a1 = fmaf(qr[d + 1], tr[d + 1], a1);
            a2 = fmaf(qr[d + 2], tr[d + 2], a2);
            a3 = fmaf(qr[d + 3], tr[d + 3], a3);
        }
        obase[o] = (a0 + a1) + (a2 + a3);
    }
}

// ---------------- fused attention (32-key tiles, warp-local softmax) ------
// sc dependencies (QK->softmax, softmax->PV) are intra-warp: row r is
// written by tids 8*(r>>3)..+7 and read by tid r, all in warp r/32.
struct AttSmem {
    float q   [128][65];   // 33280 B
    float sc  [128][33];   // 16896 B
    float kv  [32][65];    //  8320 B
    float rwsT[32][128];   // 16384 B (transposed: [key][query])
    float corr[128];       //   512 B
    float invl[128];       //   512 B
};                         // 75904 B -> 3 blocks/SM with max carveout

__global__ __launch_bounds__(128, 3) void attn_kernel()
{
    extern __shared__ char smem_raw[];
    AttSmem& sm = *reinterpret_cast<AttSmem*>(smem_raw);

    const int bh  = blockIdx.y;
    const int s0  = blockIdx.x * 128;
    const int tid = threadIdx.x;
    const int qty = tid >> 3;
    const int qtx = tid & 7;
    const float scale = 0.125f;

    {
        const float4* qp = (const float4*)(g_q + ((size_t)bh * S + s0) * HD);
#pragma unroll
        for (int u = 0; u < 16; u++) {
            const int idx4 = tid + 128 * u;
            float4 t = qp[idx4];
            const int r = idx4 >> 4, c = (idx4 & 15) * 4;
            sm.q[r][c + 0] = t.x * scale;
            sm.q[r][c + 1] = t.y * scale;
            sm.q[r][c + 2] = t.z * scale;
            sm.q[r][c + 3] = t.w * scale;
        }
    }
    {   // stage rel_w transposed: thread t reads row (s0+t), scatters to col t
        const float4* rp = (const float4*)(g_relw + ((size_t)bh * S + s0 + tid) * 32);
#pragma unroll
        for (int u = 0; u < 8; u++) {
            float4 t = rp[u];
            sm.rwsT[4 * u + 0][tid] = t.x;
            sm.rwsT[4 * u + 1][tid] = t.y;
            sm.rwsT[4 * u + 2][tid] = t.z;
            sm.rwsT[4 * u + 3][tid] = t.w;
        }
    }

    float o[8][8];
#pragma unroll
    for (int i = 0; i < 8; i++)
#pragma unroll
        for (int j = 0; j < 8; j++) o[i][j] = 0.f;

    float mrun = -1e30f, lrun = 0.f;

    // preload K tile 0 into registers
    float4 kreg[4];
    {
        const float4* kp = (const float4*)(g_k + ((size_t)bh * S) * HD);
#pragma unroll
        for (int u = 0; u < 4; u++) kreg[u] = kp[tid + 128 * u];
    }

    for (int kt0 = 0; kt0 < S; kt0 += 32) {
        __syncthreads();            // kv free (prev PV done)

        // ---- stage prefetched K tile ----
#pragma unroll
        for (int u = 0; u < 4; u++) {
            const int idx4 = tid + 128 * u;
            const int r = idx4 >> 4, c = (idx4 & 15) * 4;
            sm.kv[r][c + 0] = kreg[u].x;
            sm.kv[r][c + 1] = kreg[u].y;
            sm.kv[r][c + 2] = kreg[u].z;
            sm.kv[r][c + 3] = kreg[u].w;
        }
        __syncthreads();

        // ---- QK micro-tile: 8q x 4k ----
        {
            float acc[8][4];
#pragma unroll
            for (int i = 0; i < 8; i++)
#pragma unroll
                for (int j = 0; j < 4; j++) acc[i][j] = 0.f;

#pragma unroll 8
            for (int kk = 0; kk < 64; kk++) {
                float a[8], b[4];
#pragma unroll
                for (int i = 0; i < 8; i++) a[i] = sm.q[qty * 8 + i][kk];
#pragma unroll
                for (int j = 0; j < 4; j++) b[j] = sm.kv[qtx * 4 + j][kk];
#pragma unroll
                for (int i = 0; i < 8; i++)
#pragma unroll
                    for (int j = 0; j < 4; j++)
                        acc[i][j] = fmaf(a[i], b[j], acc[i][j]);
            }
#pragma unroll
            for (int i = 0; i < 8; i++)
#pragma unroll
                for (int j = 0; j < 4; j++)
                    sm.sc[qty * 8 + i][qtx * 4 + j] = acc[i][j];
        }

        // ---- V + next-K prefetch (LDG in flight through softmax) ----
        float4 vreg[4];
        {
            const float4* vp = (const float4*)(g_v + ((size_t)bh * S + kt0) * HD);
#pragma unroll
            for (int u = 0; u < 4; u++) vreg[u] = vp[tid + 128 * u];
            const int ktn = (kt0 + 32 < S) ? kt0 + 32 : kt0;
            const float4* kp = (const float4*)(g_k + ((size_t)bh * S + ktn) * HD);
#pragma unroll
            for (int u = 0; u < 4; u++) kreg[u] = kp[tid + 128 * u];
        }

        __syncwarp();               // sc handoff is intra-warp: overlap softmax
                                    // with other warps' QK tails
        // ---- softmax (rhb folded into subtracted max) ----
        {
            const float rhb = g_relh[((size_t)bh * S + s0 + tid) * 32 + (kt0 >> 5)];
            float s[32];
            float mx = -1e30f;
#pragma unroll
            for (int j = 0; j < 32; j++) {
                s[j] = sm.sc[tid][j] + sm.rwsT[j][tid];   // true logit minus rhb
                mx = fmaxf(mx, s[j]);
            }
            const float mnew = fmaxf(mrun, mx + rhb);     // true running max
            const float meff = mnew - rhb;
            const float cf = __expf(mrun - mnew);
            lrun *= cf;
#pragma unroll
            for (int j = 0; j < 32; j++) {
                const float p = __expf(s[j] - meff);
                lrun += p;
                sm.sc[tid][j] = p;
            }
            mrun = mnew;
            sm.corr[tid] = cf;
            if (kt0 == S - 32) sm.invl[tid] = 1.f / lrun;
        }

        __syncthreads();            // all warps past QK kv reads
        // ---- stage V ----
#pragma unroll
        for (int u = 0; u < 4; u++) {
            const int idx4 = tid + 128 * u;
            const int r = idx4 >> 4, c = (idx4 & 15) * 4;
            sm.kv[r][c + 0] = vreg[u].x;
            sm.kv[r][c + 1] = vreg[u].y;
            sm.kv[r][c + 2] = vreg[u].z;
            sm.kv[r][c + 3] = vreg[u].w;
        }
        __syncthreads();            // V visible (sc/corr handoff is intra-warp)

        // ---- PV micro-tile: 8q x 8d ----
        {
            if (kt0 > 0) {          // tile 0: o is all zero, skip rescale
                float c8[8];
#pragma unroll
                for (int i = 0; i < 8; i++) c8[i] = sm.corr[qty * 8 + i];
#pragma unroll
                for (int i = 0; i < 8; i++)
#pragma unroll
                    for (int j = 0; j < 8; j++) o[i][j] *= c8[i];
            }

#pragma unroll 4
            for (int key = 0; key < 32; key++) {
                float vv[8];
#pragma unroll
                for (int j = 0; j < 4; j++) vv[j]     = sm.kv[key][qtx * 4 + j];
#pragma unroll
                for (int j = 0; j < 4; j++) vv[4 + j] = sm.kv[key][32 + qtx * 4 + j];
#pragma unroll
                for (int i = 0; i < 8; i++) {
                    const float p = sm.sc[qty * 8 + i][key];
#pragma unroll
                    for (int j = 0; j < 8; j++)
                        o[i][j] = fmaf(p, vv[j], o[i][j]);
                }
            }
        }
    }

    // ---- epilogue ----
    {
        float inv8[8];
#pragma unroll
        for (int i = 0; i < 8; i++) inv8[i] = sm.invl[qty * 8 + i];
        const int b = bh / NUM_HEADS, head = bh % NUM_HEADS;
#pragma unroll
        for (int i = 0; i < 8; i++) {
            const int qrow = s0 + qty * 8 + i;
            float* dst = g_att + ((size_t)(b * S + qrow)) * C + head * HD;
            float4 t0, t1;
            t0.x = o[i][0] * inv8[i];
            t0.y = o[i][1] * inv8[i];
            t0.z = o[i][2] * inv8[i];
            t0.w = o[i][3] * inv8[i];
            t1.x = o[i][4] * inv8[i];
            t1.y = o[i][5] * inv8[i];
            t1.z = o[i][6] * inv8[i];
            t1.w = o[i][7] * inv8[i];
            *(float4*)(dst + qtx * 4)      = t0;
            *(float4*)(dst + 32 + qtx * 4) = t1;
        }
    }
}

// ---------------- launch ----------------
extern "C" void kernel_launch(void* const* d_in, const int* in_sizes, int n_in,
                              void* d_out, int out_size)
{
    const float* x     = (const float*)d_in[0];
    const float* wqkv  = (const float*)d_in[1];
    const float* bqkv  = (const float*)d_in[2];
    const float* rph   = (const float*)d_in[3];
    const float* rpw   = (const float*)d_in[4];
    const float* wproj = (const float*)d_in[5];
    const float* bproj = (const float*)d_in[6];
    float* out = (float*)d_out;

    // 1) QKV GEMM -> g_q/g_k/g_v  (M=8192, N=2304, K=768)
    dim3 g1(2304 / 128, 8192 / 128);
    gemm_k<0><<<g1, 256>>>(x, wqkv, bqkv, nullptr, BATCH * S, 3 * C, C);

    // 2) relative-position bias tables (h and w in one launch)
    rel_kernel<<<dim3(32, BHN, 2), 256>>>(rph, rpw);

    // 3) fused attention -> g_att
    const size_t attn_smem = sizeof(AttSmem);
    cudaFuncSetAttribute(attn_kernel, cudaFuncAttributeMaxDynamicSharedMemorySize,
                         (int)attn_smem);
    cudaFuncSetAttribute(attn_kernel, cudaFuncAttributePreferredSharedMemoryCarveout,
                         100);   // max shared carveout -> 3 blocks/SM
    attn_kernel<<<dim3(S / 128, BHN), 128, attn_smem>>>();

    // 4) output projection -> d_out  (M=8192, N=768, K=768)
    dim3 g2(768 / 128, 8192 / 128);
    gemm_k<1><<<g2, 256>>>(nullptr, wproj, bproj, out, BATCH * S, C, C);
}

// round 14
// speedup vs baseline: 1.0091x; 1.0079x over previous
#include <cuda_runtime.h>

#define NUM_HEADS 12
#define HD 64
#define BATCH 8
#define HH 32
#define WW 32
#define S 1024          // HH*WW
#define C 768
#define BHN 96          // BATCH*NUM_HEADS
#define LOG2E 1.44269504088896340736f

// ---------------- scratch (no allocations allowed) ----------------
__device__ __align__(16) float g_q[(size_t)BHN * S * HD];
__device__ __align__(16) float g_k[(size_t)BHN * S * HD];
__device__ __align__(16) float g_v[(size_t)BHN * S * HD];
__device__ __align__(16) float g_relh[(size_t)BHN * S * HH];   // pre-scaled by LOG2E
__device__ __align__(16) float g_relw[(size_t)BHN * S * WW];   // pre-scaled by LOG2E
__device__ __align__(16) float g_att[(size_t)BATCH * S * C];

__device__ __forceinline__ float ex2(float x) {
    float r;
    asm("ex2.approx.ftz.f32 %0, %1;" : "=f"(r) : "f"(x));
    return r;
}

// ------- 128x128x8 fp32 GEMM, 8x8 microtile, double-buffered smem ---------
// MODE 0: C = A @ B + bias, scatter into g_q/g_k/g_v  (A = x, B = w_qkv)
// MODE 1: C = g_att @ B + bias -> Cout (row-major)     (B = w_proj)
template <int MODE>
__global__ __launch_bounds__(256) void gemm_k(const float* __restrict__ A,
                                              const float* __restrict__ B,
                                              const float* __restrict__ bias,
                                              float* __restrict__ Cout,
                                              int M, int N, int K)
{
    __shared__ __align__(16) float As[2][8][128];
    __shared__ __align__(16) float Bs[2][8][128];

    const float* Ap = (MODE == 1) ? (const float*)g_att : A;

    const int tid = threadIdx.x;
    const int tx = tid & 15, ty = tid >> 4;
    const int bm = blockIdx.y * 128, bn = blockIdx.x * 128;

    float acc[8][8];
#pragma unroll
    for (int i = 0; i < 8; i++)
#pragma unroll
        for (int j = 0; j < 8; j++) acc[i][j] = 0.f;

    const int arow = tid >> 1, acol = (tid & 1) * 4;
    const int brow = tid >> 5, bcol = (tid & 31) * 4;
    const int klast = K - 8;

    // prologue: chunk 0 -> buf 0; preload chunk 1 into regs
    {
        float4 av = *(const float4*)(Ap + (size_t)(bm + arow) * K + acol);
        float4 bv = *(const float4*)(B + (size_t)brow * N + bn + bcol);
        As[0][acol + 0][arow] = av.x;
        As[0][acol + 1][arow] = av.y;
        As[0][acol + 2][arow] = av.z;
        As[0][acol + 3][arow] = av.w;
        *(float4*)&Bs[0][brow][bcol] = bv;
    }
    float4 av = *(const float4*)(Ap + (size_t)(bm + arow) * K + 8 + acol);
    float4 bv = *(const float4*)(B + (size_t)(8 + brow) * N + bn + bcol);
    __syncthreads();

    int buf = 0;
    for (int k0 = 0; k0 < K; k0 += 8) {
        const int nb = buf ^ 1;
        As[nb][acol + 0][arow] = av.x;
        As[nb][acol + 1][arow] = av.y;
        As[nb][acol + 2][arow] = av.z;
        As[nb][acol + 3][arow] = av.w;
        *(float4*)&Bs[nb][brow][bcol] = bv;

        const int kn = (k0 + 16 <= klast) ? k0 + 16 : klast;
        av = *(const float4*)(Ap + (size_t)(bm + arow) * K + kn + acol);
        bv = *(const float4*)(B + (size_t)(kn + brow) * N + bn + bcol);

#pragma unroll
        for (int kk = 0; kk < 8; kk++) {
            float a[8], b[8];
            *(float4*)(a)     = *(const float4*)&As[buf][kk][ty * 8];
            *(float4*)(a + 4) = *(const float4*)&As[buf][kk][ty * 8 + 4];
            *(float4*)(b)     = *(const float4*)&Bs[buf][kk][tx * 8];
            *(float4*)(b + 4) = *(const float4*)&Bs[buf][kk][tx * 8 + 4];
#pragma unroll
            for (int i = 0; i < 8; i++)
#pragma unroll
                for (int j = 0; j < 8; j++)
                    acc[i][j] = fmaf(a[i], b[j], acc[i][j]);
        }
        __syncthreads();
        buf = nb;
    }

#pragma unroll
    for (int i = 0; i < 8; i++) {
        const int m = bm + ty * 8 + i;
        const int b = m >> 10, s = m & 1023;
#pragma unroll
        for (int j = 0; j < 8; j++) {
            const int n = bn + tx * 8 + j;
            const float v = acc[i][j] + bias[n];
            if (MODE == 0) {
                const int t   = n / C;          // 0:q 1:k 2:v
                const int rem = n - t * C;
                const int hh  = rem >> 6;       // head
                const int d   = rem & 63;
                float* dst = (t == 0) ? g_q : (t == 1) ? g_k : g_v;
                dst[((size_t)(b * NUM_HEADS + hh) * S + s) * HD + d] = v;
            } else {
                Cout[(size_t)m * N + n] = v;
            }
        }
    }
}

// ---------------- relative-position bias tables (output x LOG2E) ----------
__global__ __launch_bounds__(256) void rel_kernel(const float* __restrict__ tabh,
                                                  const float* __restrict__ tabw)
{
    __shared__ float tab[63][65];
    __shared__ float qs[32][65];
    const int bh = blockIdx.y;
    const int h  = blockIdx.x;
    const int mode = blockIdx.z;
    const int tid = threadIdx.x;
    const float* table = mode ? tabw : tabh;

    for (int idx = tid; idx < 63 * 64; idx += 256)
        tab[idx >> 6][idx & 63] = table[idx];
    const float* qbase = g_q + ((size_t)bh * S + h * 32) * HD;
    for (int idx = tid; idx < 32 * 64; idx += 256)
        qs[idx >> 6][idx & 63] = qbase[idx];
    __syncthreads();

    float* out = (mode == 0) ? g_relh : g_relw;
    float* obase = out + ((size_t)bh * 32 + h) * 32 * 32;

    for (int o = tid; o < 1024; o += 256) {
        const int w = o >> 5, j = o & 31;
        const int row = (mode == 0) ? (h - j + 31) : (w - j + 31);
        const float* qr = qs[w];
        const float* tr = tab[row];
        float a0 = 0.f, a1 = 0.f, a2 = 0.f, a3 = 0.f;
#pragma unroll
        for (int d = 0; d < 64; d += 4) {
            a0 = fmaf(qr[d + 0], tr[d + 0], a0);
            a1 = fmaf(qr[d + 1], tr[d + 1], a1);
            a2 = fmaf(qr[d + 2], tr[d + 2], a2);
            a3 = fmaf(qr[d + 3], tr[d + 3], a3);
        }
        obase[o] = ((a0 + a1) + (a2 + a3)) * LOG2E;   // log2-domain bias
    }
}

// ---------------- fused attention (log2-domain softmax, R11 structure) ----
// Scores are computed in log2 units: q staged x(scale*LOG2E), biases already
// xLOG2E, so every exp is a bare EX2 (no pre-multiply).
struct AttSmem {
    float q   [128][65];   // 33280 B
    float sc  [128][33];   // 16896 B
    float kv  [32][65];    //  8320 B
    float rwsT[32][128];   // 16384 B (transposed: [key][query])
    float corr[128];       //   512 B
    float invl[128];       //   512 B
};                         // 75904 B -> 3 blocks/SM with max carveout

__global__ __launch_bounds__(128, 3) void attn_kernel()
{
    extern __shared__ char smem_raw[];
    AttSmem& sm = *reinterpret_cast<AttSmem*>(smem_raw);

    const int bh  = blockIdx.y;
    const int s0  = blockIdx.x * 128;
    const int tid = threadIdx.x;
    const int qty = tid >> 3;
    const int qtx = tid & 7;
    const float scale = 0.125f * LOG2E;   // fold log2e into q staging

    {
        const float4* qp = (const float4*)(g_q + ((size_t)bh * S + s0) * HD);
#pragma unroll
        for (int u = 0; u < 16; u++) {
            const int idx4 = tid + 128 * u;
            float4 t = qp[idx4];
            const int r = idx4 >> 4, c = (idx4 & 15) * 4;
            sm.q[r][c + 0] = t.x * scale;
            sm.q[r][c + 1] = t.y * scale;
            sm.q[r][c + 2] = t.z * scale;
            sm.q[r][c + 3] = t.w * scale;
        }
    }
    {   // stage rel_w transposed (already xLOG2E)
        const float4* rp = (const float4*)(g_relw + ((size_t)bh * S + s0 + tid) * 32);
#pragma unroll
        for (int u = 0; u < 8; u++) {
            float4 t = rp[u];
            sm.rwsT[4 * u + 0][tid] = t.x;
            sm.rwsT[4 * u + 1][tid] = t.y;
            sm.rwsT[4 * u + 2][tid] = t.z;
            sm.rwsT[4 * u + 3][tid] = t.w;
        }
    }

    float o[8][8];
#pragma unroll
    for (int i = 0; i < 8; i++)
#pragma unroll
        for (int j = 0; j < 8; j++) o[i][j] = 0.f;

    float mrun = -1e30f, lrun = 0.f;

    // preload K tile 0 into registers
    float4 kreg[4];
    {
        const float4* kp = (const float4*)(g_k + ((size_t)bh * S) * HD);
#pragma unroll
        for (int u = 0; u < 4; u++) kreg[u] = kp[tid + 128 * u];
    }

    for (int kt0 = 0; kt0 < S; kt0 += 32) {
        __syncthreads();            // kv free (prev PV done)

        // ---- stage prefetched K tile ----
#pragma unroll
        for (int u = 0; u < 4; u++) {
            const int idx4 = tid + 128 * u;
            const int r = idx4 >> 4, c = (idx4 & 15) * 4;
            sm.kv[r][c + 0] = kreg[u].x;
            sm.kv[r][c + 1] = kreg[u].y;
            sm.kv[r][c + 2] = kreg[u].z;
            sm.kv[r][c + 3] = kreg[u].w;
        }
        __syncthreads();

        // ---- QK micro-tile: 8q x 4k (scores in log2 units) ----
        {
            float acc[8][4];
#pragma unroll
            for (int i = 0; i < 8; i++)
#pragma unroll
                for (int j = 0; j < 4; j++) acc[i][j] = 0.f;

#pragma unroll 8
            for (int kk = 0; kk < 64; kk++) {
                float a[8], b[4];
#pragma unroll
                for (int i = 0; i < 8; i++) a[i] = sm.q[qty * 8 + i][kk];
#pragma unroll
                for (int j = 0; j < 4; j++) b[j] = sm.kv[qtx * 4 + j][kk];
#pragma unroll
                for (int i = 0; i < 8; i++)
#pragma unroll
                    for (int j = 0; j < 4; j++)
                        acc[i][j] = fmaf(a[i], b[j], acc[i][j]);
            }
#pragma unroll
            for (int i = 0; i < 8; i++)
#pragma unroll
                for (int j = 0; j < 4; j++)
                    sm.sc[qty * 8 + i][qtx * 4 + j] = acc[i][j];
        }
        __syncthreads();

        // ---- softmax (log2 domain; rhb folded into subtracted max) ----
        {
            const float4* vp = (const float4*)(g_v + ((size_t)bh * S + kt0) * HD);
            float4 vreg[4];
#pragma unroll
            for (int u = 0; u < 4; u++) vreg[u] = vp[tid + 128 * u];

            const int ktn = (kt0 + 32 < S) ? kt0 + 32 : kt0;
            const float4* kp = (const float4*)(g_k + ((size_t)bh * S + ktn) * HD);
#pragma unroll
            for (int u = 0; u < 4; u++) kreg[u] = kp[tid + 128 * u];

            const float rhb = g_relh[((size_t)bh * S + s0 + tid) * 32 + (kt0 >> 5)];
            float s[32];
            float mx = -1e30f;
#pragma unroll
            for (int j = 0; j < 32; j++) {
                s[j] = sm.sc[tid][j] + sm.rwsT[j][tid];   // log2 logit minus rhb
                mx = fmaxf(mx, s[j]);
            }
            const float mnew = fmaxf(mrun, mx + rhb);     // running max (log2)
            const float meff = mnew - rhb;
            const float cf = ex2(mrun - mnew);            // bare EX2
            lrun *= cf;
#pragma unroll
            for (int j = 0; j < 32; j++) {
                const float p = ex2(s[j] - meff);         // bare EX2
                lrun += p;
                sm.sc[tid][j] = p;
            }
            mrun = mnew;
            sm.corr[tid] = cf;
            if (kt0 == S - 32) sm.invl[tid] = 1.f / lrun;

            // stage V (QK reads of kv finished before last sync)
#pragma unroll
            for (int u = 0; u < 4; u++) {
                const int idx4 = tid + 128 * u;
                const int r = idx4 >> 4, c = (idx4 & 15) * 4;
                sm.kv[r][c + 0] = vreg[u].x;
                sm.kv[r][c + 1] = vreg[u].y;
                sm.kv[r][c + 2] = vreg[u].z;
                sm.kv[r][c + 3] = vreg[u].w;
            }
        }
        __syncthreads();

        // ---- PV micro-tile: 8q x 8d ----
        {
            if (kt0 > 0) {          // tile 0: o is all zero, skip rescale
                float c8[8];
#pragma unroll
                for (int i = 0; i < 8; i++) c8[i] = sm.corr[qty * 8 + i];
#pragma unroll
                for (int i = 0; i < 8; i++)
#pragma unroll
                    for (int j = 0; j < 8; j++) o[i][j] *= c8[i];
            }

#pragma unroll 4
            for (int key = 0; key < 32; key++) {
                float vv[8];
#pragma unroll
                for (int j = 0; j < 4; j++) vv[j]     = sm.kv[key][qtx * 4 + j];
#pragma unroll
                for (int j = 0; j < 4; j++) vv[4 + j] = sm.kv[key][32 + qtx * 4 + j];
#pragma unroll
                for (int i = 0; i < 8; i++) {
                    const float p = sm.sc[qty * 8 + i][key];
#pragma unroll
                    for (int j = 0; j < 8; j++)
                        o[i][j] = fmaf(p, vv[j], o[i][j]);
                }
            }
        }
    }

    // ---- epilogue ----
    {
        float inv8[8];
#pragma unroll
        for (int i = 0; i < 8; i++) inv8[i] = sm.invl[qty * 8 + i];
        const int b = bh / NUM_HEADS, head = bh % NUM_HEADS;
#pragma unroll
        for (int i = 0; i < 8; i++) {
            const int qrow = s0 + qty * 8 + i;
            float* dst = g_att + ((size_t)(b * S + qrow)) * C + head * HD;
            float4 t0, t1;
            t0.x = o[i][0] * inv8[i];
            t0.y = o[i][1] * inv8[i];
            t0.z = o[i][2] * inv8[i];
            t0.w = o[i][3] * inv8[i];
            t1.x = o[i][4] * inv8[i];
            t1.y = o[i][5] * inv8[i];
            t1.z = o[i][6] * inv8[i];
            t1.w = o[i][7] * inv8[i];
            *(float4*)(dst + qtx * 4)      = t0;
            *(float4*)(dst + 32 + qtx * 4) = t1;
        }
    }
}

// ---------------- launch ----------------
extern "C" void kernel_launch(void* const* d_in, const int* in_sizes, int n_in,
                              void* d_out, int out_size)
{
    const float* x     = (const float*)d_in[0];
    const float* wqkv  = (const float*)d_in[1];
    const float* bqkv  = (const float*)d_in[2];
    const float* rph   = (const float*)d_in[3];
    const float* rpw   = (const float*)d_in[4];
    const float* wproj = (const float*)d_in[5];
    const float* bproj = (const float*)d_in[6];
    float* out = (float*)d_out;

    // 1) QKV GEMM -> g_q/g_k/g_v  (M=8192, N=2304, K=768)
    dim3 g1(2304 / 128, 8192 / 128);
    gemm_k<0><<<g1, 256>>>(x, wqkv, bqkv, nullptr, BATCH * S, 3 * C, C);

    // 2) relative-position bias tables (h and w in one launch, xLOG2E)
    rel_kernel<<<dim3(32, BHN, 2), 256>>>(rph, rpw);

    // 3) fused attention -> g_att
    const size_t attn_smem = sizeof(AttSmem);
    cudaFuncSetAttribute(attn_kernel, cudaFuncAttributeMaxDynamicSharedMemorySize,
                         (int)attn_smem);
    cudaFuncSetAttribute(attn_kernel, cudaFuncAttributePreferredSharedMemoryCarveout,
                         100);   // max shared carveout -> 3 blocks/SM
    attn_kernel<<<dim3(S / 128, BHN), 128, attn_smem>>>();

    // 4) output projection -> d_out  (M=8192, N=768, K=768)
    dim3 g2(768 / 128, 8192 / 128);
    gemm_k<1><<<g2, 256>>>(nullptr, wproj, bproj, out, BATCH * S, C, C);
}